// round 7
// baseline (speedup 1.0000x reference)
#include <cuda_runtime.h>
#include <cuda_fp16.h>
#include <math.h>
#include <stdint.h>

#define NT     256
#define NF     256
#define KD     128

#define INVD4  0.2973017787506803f    // 128^(-1/4)
#define HC     0.04419417382415922f   // 1/(2*sqrt(128))

#define BFF_U32 16384                 // B fragments (fp16): 64 KB
#define AFF_U32 8192                  // A fragments (fp16, M=128): 32 KB
#define STG_F   16384                 // fp32 staging [128][128]: 64 KB

// ---------------- globals -------------------------------------------------------
static __device__ unsigned g_max_u;
static __device__ float    g_maxval;
static __device__ float    g_sumKraw[NF];
static __device__ float    g_sumK[NF];

__device__ __forceinline__ unsigned f2u(float f) {
    unsigned b = __float_as_uint(f);
    return (b & 0x80000000u) ? ~b : (b | 0x80000000u);
}
__device__ __forceinline__ float u2f(unsigned u) {
    return (u & 0x80000000u) ? __uint_as_float(u ^ 0x80000000u) : __uint_as_float(~u);
}

__global__ void sp_init() {
    if (threadIdx.x == 0) g_max_u = 0u;
    g_sumKraw[threadIdx.x] = 0.f;
}
__global__ void sp_finalize(float neps) {
    const float gmax = u2f(g_max_u);
    if (threadIdx.x == 0) g_maxval = gmax;
    g_sumK[threadIdx.x] = (g_sumKraw[threadIdx.x] * expf(-gmax) + neps) * 0.0625f;
}

// ---------------- low-level helpers ---------------------------------------------
__device__ __forceinline__ uint32_t smem_u32(const void* p) {
    uint32_t a;
    asm("{ .reg .u64 t; cvta.to.shared.u64 t, %1; cvt.u32.u64 %0, t; }" : "=r"(a) : "l"(p));
    return a;
}
__device__ __forceinline__ void cp_async16(uint32_t dst, const void* src) {
    asm volatile("cp.async.ca.shared.global [%0], [%1], 16;" :: "r"(dst), "l"(src));
}
#define CP_COMMIT() asm volatile("cp.async.commit_group;" ::: "memory")
#define CP_WAIT0()  asm volatile("cp.async.wait_group 0;" ::: "memory")

__device__ __forceinline__ void mma_f16(float* d, const uint4& a, uint32_t b0, uint32_t b1) {
    asm volatile(
        "mma.sync.aligned.m16n8k16.row.col.f32.f16.f16.f32 "
        "{%0,%1,%2,%3}, {%4,%5,%6,%7}, {%8,%9}, {%0,%1,%2,%3};\n"
        : "+f"(d[0]), "+f"(d[1]), "+f"(d[2]), "+f"(d[3])
        : "r"(a.x), "r"(a.y), "r"(a.z), "r"(a.w), "r"(b0), "r"(b1));
}

// load omega (scaled, fp16) into fragment-major B (one-time per kernel)
__device__ __forceinline__ void load_B_h(const float* __restrict__ omg,
                                         uint32_t* __restrict__ Bff, int tid) {
    __half* Bh = (__half*)Bff;
    for (int i = tid; i < KD * NF; i += NT) {
        const int k = i >> 8, n = i & 255;
        const __half hv = __float2half(omg[i] * INVD4);
        const int np = n >> 3, npair = np >> 1, ks = k >> 4;
        const int lane = ((n & 7) << 2) | ((k & 7) >> 1);
        const int slot = ((np & 1) << 1) | ((k >> 3) & 1);
        const int u32idx = ((npair * 8 + ks) * 32 + lane) * 4 + slot;
        Bh[u32idx * 2 + (k & 1)] = hv;
    }
}

// convert one staging row sr (fp32, 128 wide) -> fp16 fragments; returns row |x|^2*HC in lane 0
__device__ __forceinline__ float conv_row(const float* __restrict__ stag, int sr,
                                          uint32_t* __restrict__ Aff, int lane) {
    const int k0 = lane << 2;
    float4 v = *(const float4*)(stag + sr * KD + k0);
    float p = v.x * v.x + v.y * v.y + v.z * v.z + v.w * v.w;
#pragma unroll
    for (int o = 16; o; o >>= 1) p += __shfl_xor_sync(0xffffffffu, p, o);
    __half2 h01 = __floats2half2_rn(v.x, v.y);
    __half2 h23 = __floats2half2_rn(v.z, v.w);
    const int mi = sr >> 4, rlo = sr & 15, ks = k0 >> 4;
    const int reg = ((rlo >> 3) & 1) | (((k0 >> 3) & 1) << 1);
    const int ls  = ((rlo & 7) << 2) | ((k0 >> 1) & 3);
    uint32_t* base = Aff + (unsigned)((mi * 8 + ks) * 32) * 4 + reg;
    base[ls * 4]       = *(uint32_t*)&h01;
    base[(ls + 1) * 4] = *(uint32_t*)&h23;
    return p * HC;
}

// 128x256x128 GEMM, 8 warps, each 64 rows x 64 cols: acc[m][jn][c]
__device__ __forceinline__ void gemm128(const uint4* __restrict__ Aff4,
                                        const uint4* __restrict__ Bff4,
                                        int wr, int wc, int lane, float acc[4][8][4]) {
#pragma unroll
    for (int m = 0; m < 4; m++)
#pragma unroll
        for (int j = 0; j < 8; j++)
#pragma unroll
            for (int c = 0; c < 4; c++) acc[m][j][c] = 0.f;
#pragma unroll
    for (int ks = 0; ks < 8; ks++) {
        uint4 a[4];
#pragma unroll
        for (int m = 0; m < 4; m++)
            a[m] = Aff4[((wr * 4 + m) * 8 + ks) * 32 + lane];
#pragma unroll
        for (int p = 0; p < 4; p++) {
            uint4 bv = Bff4[((wc * 4 + p) * 8 + ks) * 32 + lane];
#pragma unroll
            for (int m = 0; m < 4; m++) {
                mma_f16(acc[m][2 * p],     a[m], bv.x, bv.y);
                mma_f16(acc[m][2 * p + 1], a[m], bv.z, bv.w);
            }
        }
    }
}

__device__ __forceinline__ float grp_sum(float v) {
    v += __shfl_xor_sync(0xffffffffu, v, 1);
    v += __shfl_xor_sync(0xffffffffu, v, 2);
    return v;
}
__device__ __forceinline__ float grp_max(float v) {
    v = fmaxf(v, __shfl_xor_sync(0xffffffffu, v, 1));
    v = fmaxf(v, __shfl_xor_sync(0xffffffffu, v, 2));
    return v;
}

// ---------------- pass 1: U_K (128 rows/tile) -> gmax + colsums(exp) ------------
__global__ void __launch_bounds__(NT, 1)
sp_kpass(const float* __restrict__ Kg, const float* __restrict__ omg, int ntiles) {
    extern __shared__ float sh[];
    uint32_t* Bff = (uint32_t*)sh;
    uint32_t* Aff = Bff + BFF_U32;
    float* stag = (float*)(Aff + AFF_U32);     // 16384 floats
    float* hrow = stag + STG_F;                // 128
    float* cs   = hrow + KD;                   // 256
    unsigned* bmax = (unsigned*)(cs + NF);

    const int tid = threadIdx.x, wid = tid >> 5, lane = tid & 31;
    const int wr = wid >> 2, wc = wid & 3;
    const uint32_t stg32 = smem_u32(stag);

    load_B_h(omg, Bff, tid);
    if (tid < NF) cs[tid] = 0.f;
    if (tid == 0) *bmax = 0u;

    int tile = blockIdx.x;
    if (tile < ntiles) {
        const size_t r0 = (size_t)tile * 128;
#pragma unroll
        for (int t = 0; t < 16; t++) {
            const int i = tid + t * NT;
            const int sr = i >> 5, ck = i & 31;
            cp_async16(stg32 + (unsigned)i * 16, Kg + (r0 + sr) * KD + ck * 4);
        }
    }
    CP_COMMIT();

    float acc[4][8][4];
    for (; tile < ntiles; tile += gridDim.x) {
        CP_WAIT0();
        __syncthreads();
#pragma unroll
        for (int t = 0; t < 16; t++) {
            const int sr = wid + t * 8;
            const float h = conv_row(stag, sr, Aff, lane);
            if (lane == 0) hrow[sr] = h;
        }
        __syncthreads();
        const int nxt = tile + gridDim.x;
        if (nxt < ntiles) {
            const size_t r0 = (size_t)nxt * 128;
#pragma unroll
            for (int t = 0; t < 16; t++) {
                const int i = tid + t * NT;
                const int sr = i >> 5, ck = i & 31;
                cp_async16(stg32 + (unsigned)i * 16, Kg + (r0 + sr) * KD + ck * 4);
            }
        }
        CP_COMMIT();

        gemm128((const uint4*)Aff, (const uint4*)Bff, wr, wc, lane, acc);

        float colp[16];
#pragma unroll
        for (int t = 0; t < 16; t++) colp[t] = 0.f;
        float lmax = -INFINITY;
#pragma unroll
        for (int m = 0; m < 4; m++) {
            const int r1 = (wr * 4 + m) * 16 + (lane >> 2);
            const float hv1 = hrow[r1], hv2 = hrow[r1 + 8];
#pragma unroll
            for (int jn = 0; jn < 8; jn++)
#pragma unroll
                for (int cc = 0; cc < 2; cc++) {
                    const float u1 = acc[m][jn][cc], u2 = acc[m][jn][2 + cc];
                    lmax = fmaxf(lmax, fmaxf(u1, u2));
                    colp[jn * 2 + cc] += __expf(u1 - hv1) + __expf(u2 - hv2);
                }
        }
#pragma unroll
        for (int t = 0; t < 16; t++) {
            float s = colp[t];
            s += __shfl_xor_sync(0xffffffffu, s, 4);
            s += __shfl_xor_sync(0xffffffffu, s, 8);
            s += __shfl_xor_sync(0xffffffffu, s, 16);
            colp[t] = s;
        }
        if (lane < 4) {
#pragma unroll
            for (int t = 0; t < 16; t++)
                atomicAdd(&cs[wc * 64 + (t >> 1) * 8 + 2 * lane + (t & 1)], colp[t]);
        }
#pragma unroll
        for (int o = 16; o; o >>= 1)
            lmax = fmaxf(lmax, __shfl_xor_sync(0xffffffffu, lmax, o));
        if (lane == 0) atomicMax(bmax, f2u(lmax));
    }
    __syncthreads();
    if (tid < NF) atomicAdd(&g_sumKraw[tid], cs[tid]);
    if (tid == 0) atomicMax(&g_max_u, *bmax);
}

// ---------------- pass 2: interleaved Q/K tile (64 logical rows), scale V -------
__global__ void __launch_bounds__(NT, 1)
sp_final(const float* __restrict__ Qg, const float* __restrict__ Kg,
         const float* __restrict__ V, const float* __restrict__ omg,
         float* __restrict__ out, int ntiles) {
    extern __shared__ float sh[];
    uint32_t* Bff = (uint32_t*)sh;
    uint32_t* Aff = Bff + BFF_U32;
    float* stag = (float*)(Aff + AFF_U32);     // 16384
    float* hq    = stag + STG_F;               // 64
    float* hk    = hq + 64;                    // 64
    float* sKs   = hk + 64;                    // 256
    float* rmarr = sKs + NF;                   // 256
    float* red0  = rmarr + 256;                // 256
    float* red1  = red0 + 256;                 // 256
    float* red2  = red1 + 256;                 // 256
    float* red3  = red2 + 256;                 // 256
    float* scal  = red3 + 256;                 // 64
    float* ssum  = scal + 64;                  // 1

    const int tid = threadIdx.x, wid = tid >> 5, lane = tid & 31;
    const int wr = wid >> 2, wc = wid & 3;
    const uint32_t stg32 = smem_u32(stag);
    const float gm = g_maxval;

    load_B_h(omg, Bff, tid);
    if (tid < NF) sKs[tid] = g_sumK[tid];
    __syncthreads();
    if (tid == 0) {
        float s = 0.f;
        for (int j = 0; j < NF; j++) s += sKs[j];
        *ssum = s;
    }

    int tile = blockIdx.x;
    if (tile < ntiles) {
        const size_t r0 = (size_t)tile * 64;
#pragma unroll
        for (int t = 0; t < 16; t++) {
            const int i = tid + t * NT;
            const int sr = i >> 5, ck = i & 31;
            const int b = sr >> 4, j = sr & 15;
            const float* src = ((j & 8) ? Kg : Qg) + (r0 + b * 8 + (j & 7)) * KD + ck * 4;
            cp_async16(stg32 + (unsigned)i * 16, src);
        }
    }
    CP_COMMIT();
    __syncthreads();
    const float ssv = *ssum;

    float acc[4][8][4];
    for (; tile < ntiles; tile += gridDim.x) {
        const size_t r0 = (size_t)tile * 64;
        CP_WAIT0();
        __syncthreads();
#pragma unroll
        for (int t = 0; t < 16; t++) {
            const int sr = wid + t * 8;
            const float h = conv_row(stag, sr, Aff, lane);
            const int lrow = ((sr >> 4) << 3) | (sr & 7);
            if (lane == 0) { if (sr & 8) hk[lrow] = h; else hq[lrow] = h; }
        }
        __syncthreads();
        const int nxt = tile + gridDim.x;
        if (nxt < ntiles) {
            const size_t nr0 = (size_t)nxt * 64;
#pragma unroll
            for (int t = 0; t < 16; t++) {
                const int i = tid + t * NT;
                const int sr = i >> 5, ck = i & 31;
                const int b = sr >> 4, j = sr & 15;
                const float* src = ((j & 8) ? Kg : Qg) + (nr0 + b * 8 + (j & 7)) * KD + ck * 4;
                cp_async16(stg32 + (unsigned)i * 16, src);
            }
        }
        CP_COMMIT();

        gemm128((const uint4*)Aff, (const uint4*)Bff, wr, wc, lane, acc);
        // acc[m][jn][0,1] = U_Q(lrow, col), acc[m][jn][2,3] = U_K(lrow, col)

        // pass 1: per-row max of U_Q
#pragma unroll
        for (int m = 0; m < 4; m++) {
            const int lrow = wr * 32 + m * 8 + (lane >> 2);
            float mx = -INFINITY;
#pragma unroll
            for (int jn = 0; jn < 8; jn++) {
                mx = fmaxf(mx, acc[m][jn][0]);
                mx = fmaxf(mx, acc[m][jn][1]);
            }
            mx = grp_max(mx);
            if ((lane & 3) == 0) rmarr[lrow * 4 + wc] = mx;
        }
        __syncthreads();

        // pass 2: W = sum eq*ek, S2 = sum eq, S3 = sum ek, T = sum eq*sK
#pragma unroll
        for (int m = 0; m < 4; m++) {
            const int lrow = wr * 32 + m * 8 + (lane >> 2);
            const float rmv = fmaxf(fmaxf(rmarr[lrow * 4], rmarr[lrow * 4 + 1]),
                                    fmaxf(rmarr[lrow * 4 + 2], rmarr[lrow * 4 + 3]));
            const float subq = hq[lrow] + rmv;
            const float subk = hk[lrow] + gm;
            float W = 0.f, S2 = 0.f, S3 = 0.f, T = 0.f;
#pragma unroll
            for (int jn = 0; jn < 8; jn++)
#pragma unroll
                for (int cc = 0; cc < 2; cc++) {
                    const int col = wc * 64 + jn * 8 + 2 * (lane & 3) + cc;
                    const float eq = __expf(acc[m][jn][cc] - subq);
                    const float ek = __expf(acc[m][jn][2 + cc] - subk);
                    W  = fmaf(eq, ek, W);
                    S2 += eq;
                    S3 += ek;
                    T  = fmaf(eq, sKs[col], T);
                }
            W = grp_sum(W); S2 = grp_sum(S2); S3 = grp_sum(S3); T = grp_sum(T);
            if ((lane & 3) == 0) {
                red0[lrow * 4 + wc] = W;  red1[lrow * 4 + wc] = S2;
                red2[lrow * 4 + wc] = S3; red3[lrow * 4 + wc] = T;
            }
        }
        __syncthreads();
        if (tid < 64) {
            const float W  = red0[tid * 4] + red0[tid * 4 + 1] + red0[tid * 4 + 2] + red0[tid * 4 + 3];
            const float S2 = red1[tid * 4] + red1[tid * 4 + 1] + red1[tid * 4 + 2] + red1[tid * 4 + 3];
            const float S3 = red2[tid * 4] + red2[tid * 4 + 1] + red2[tid * 4 + 2] + red2[tid * 4 + 3];
            const float T  = red3[tid * 4] + red3[tid * 4 + 1] + red3[tid * 4 + 2] + red3[tid * 4 + 3];
            const float w  = (W + 1e-4f * (S2 + S3) + 2.56e-6f) * (1.f / 256.f);
            const float nm = (T + 1e-4f * ssv) * 0.0625f + 1e-8f;
            scal[tid] = w / nm;
        }
        __syncthreads();

        const float4* Vg = (const float4*)(V + r0 * KD);
        float4* Og = (float4*)(out + r0 * KD);
#pragma unroll
        for (int t = 0; t < 8; t++) {
            const int i = tid + t * NT;
            const float s = scal[i >> 5];
            float4 v = Vg[i];
            v.x *= s; v.y *= s; v.z *= s; v.w *= s;
            Og[i] = v;
        }
    }
}

// --------------------------------- host -----------------------------------------
extern "C" void kernel_launch(void* const* d_in, const int* in_sizes, int n_in,
                              void* d_out, int out_size) {
    const float* Q   = (const float*)d_in[0];
    const float* K   = (const float*)d_in[1];
    const float* V   = (const float*)d_in[2];
    const float* omg = (const float*)d_in[3];
    float* out = (float*)d_out;

    const int N = in_sizes[0] / KD;
    const int ntK = N / 128;
    const int ntF = N / 64;

    int dev = 0, sms = 148;
    cudaGetDevice(&dev);
    cudaDeviceGetAttribute(&sms, cudaDevAttrMultiProcessorCount, dev);
    const int gK = sms < ntK ? sms : ntK;
    const int gF = sms < ntF ? sms : ntF;

    const size_t base = (size_t)(BFF_U32 + AFF_U32) * 4 + (size_t)STG_F * 4;
    const size_t smK = base + (KD + NF + 4) * sizeof(float);
    const size_t smF = base + (64 * 2 + NF + 256 * 5 + 64 + 8) * sizeof(float);
    cudaFuncSetAttribute(sp_kpass, cudaFuncAttributeMaxDynamicSharedMemorySize, (int)smK);
    cudaFuncSetAttribute(sp_final, cudaFuncAttributeMaxDynamicSharedMemorySize, (int)smF);

    sp_init<<<1, NF>>>();
    sp_kpass<<<gK, NT, smK>>>(K, omg, ntK);
    sp_finalize<<<1, NF>>>((float)N * 1e-4f);
    sp_final<<<gF, NT, smF>>>(Q, K, V, omg, out, ntF);
}

// round 8
// speedup vs baseline: 1.2373x; 1.2373x over previous
#include <cuda_runtime.h>
#include <cuda_fp16.h>
#include <math.h>
#include <stdint.h>

#define NT     256
#define NF     256
#define KD     128

#define INVD4  0.2973017787506803f    // 128^(-1/4)
#define HC     0.04419417382415922f   // 1/(2*sqrt(128))

#define BFF_U32 16384                 // B fragments (fp16): 64 KB
#define AFF_U32 4096                  // A fragments (fp16, 64 phys rows): 16 KB

// ---------------- globals -------------------------------------------------------
static __device__ unsigned g_max_u;
static __device__ float    g_maxval;
static __device__ float    g_sumKraw[NF];
static __device__ float    g_sumK[NF];

__device__ __forceinline__ unsigned f2u(float f) {
    unsigned b = __float_as_uint(f);
    return (b & 0x80000000u) ? ~b : (b | 0x80000000u);
}
__device__ __forceinline__ float u2f(unsigned u) {
    return (u & 0x80000000u) ? __uint_as_float(u ^ 0x80000000u) : __uint_as_float(~u);
}

__global__ void sp_init() {
    if (threadIdx.x == 0) g_max_u = 0u;
    g_sumKraw[threadIdx.x] = 0.f;
}
__global__ void sp_finalize(float neps) {
    const float gmax = u2f(g_max_u);
    if (threadIdx.x == 0) g_maxval = gmax;
    g_sumK[threadIdx.x] = (g_sumKraw[threadIdx.x] * expf(-gmax) + neps) * 0.0625f;
}

// ---------------- fp16 mma machinery --------------------------------------------
__device__ __forceinline__ void mma_f16(float* d, const uint4& a, uint32_t b0, uint32_t b1) {
    asm volatile(
        "mma.sync.aligned.m16n8k16.row.col.f32.f16.f16.f32 "
        "{%0,%1,%2,%3}, {%4,%5,%6,%7}, {%8,%9}, {%0,%1,%2,%3};\n"
        : "+f"(d[0]), "+f"(d[1]), "+f"(d[2]), "+f"(d[3])
        : "r"(a.x), "r"(a.y), "r"(a.z), "r"(a.w), "r"(b0), "r"(b1));
}

// load omega (scaled, fp16) into fragment-major B (one-time per kernel)
__device__ __forceinline__ void load_B_h(const float* __restrict__ omg,
                                         uint32_t* __restrict__ Bff, int tid) {
    __half* Bh = (__half*)Bff;
    for (int i = tid; i < KD * NF; i += NT) {
        const int k = i >> 8, n = i & 255;
        const __half hv = __float2half(omg[i] * INVD4);
        const int np = n >> 3, npair = np >> 1, ks = k >> 4;
        const int lane = ((n & 7) << 2) | ((k & 7) >> 1);
        const int slot = ((np & 1) << 1) | ((k >> 3) & 1);
        const int u32idx = ((npair * 8 + ks) * 32 + lane) * 4 + slot;
        Bh[u32idx * 2 + (k & 1)] = hv;
    }
}

// store one row's 4 fp32 values (at k0 = lane*4) into fp16 fragments for phys row sr
__device__ __forceinline__ void frag_store(uint32_t* __restrict__ Aff, int sr, int lane,
                                           const float4& v) {
    __half2 h01 = __floats2half2_rn(v.x, v.y);
    __half2 h23 = __floats2half2_rn(v.z, v.w);
    const int k0 = lane << 2;
    const int mi = sr >> 4, rlo = sr & 15, ks = k0 >> 4;
    const int reg = ((rlo >> 3) & 1) | (((k0 >> 3) & 1) << 1);
    const int ls  = ((rlo & 7) << 2) | ((k0 >> 1) & 3);
    uint32_t* base = Aff + (unsigned)((mi * 8 + ks) * 32) * 4 + reg;
    base[ls * 4]       = *(uint32_t*)&h01;
    base[(ls + 1) * 4] = *(uint32_t*)&h23;
}

// 64(phys)x256x128 GEMM, 8 warps, warp (wr,wc) owns 32 phys rows x 64 cols
__device__ __forceinline__ void gemm_tile(const uint4* __restrict__ Aff4,
                                          const uint4* __restrict__ Bff4,
                                          int wr, int wc, int lane, float acc[2][8][4]) {
#pragma unroll
    for (int i = 0; i < 2; i++)
#pragma unroll
        for (int j = 0; j < 8; j++)
#pragma unroll
            for (int c = 0; c < 4; c++) acc[i][j][c] = 0.f;
#pragma unroll
    for (int ks = 0; ks < 8; ks++) {
        uint4 a0 = Aff4[((wr * 2) * 8 + ks) * 32 + lane];
        uint4 a1 = Aff4[((wr * 2 + 1) * 8 + ks) * 32 + lane];
#pragma unroll
        for (int p = 0; p < 4; p++) {
            uint4 bv = Bff4[((wc * 4 + p) * 8 + ks) * 32 + lane];
            mma_f16(acc[0][2 * p],     a0, bv.x, bv.y);
            mma_f16(acc[0][2 * p + 1], a0, bv.z, bv.w);
            mma_f16(acc[1][2 * p],     a1, bv.x, bv.y);
            mma_f16(acc[1][2 * p + 1], a1, bv.z, bv.w);
        }
    }
}

__device__ __forceinline__ float grp_sum(float v) {
    v += __shfl_xor_sync(0xffffffffu, v, 1);
    v += __shfl_xor_sync(0xffffffffu, v, 2);
    return v;
}
__device__ __forceinline__ float grp_max(float v) {
    v = fmaxf(v, __shfl_xor_sync(0xffffffffu, v, 1));
    v = fmaxf(v, __shfl_xor_sync(0xffffffffu, v, 2));
    return v;
}

// ---------------- pass 1: U_K (64 rows/tile) -> gmax + colsums(exp) -------------
__global__ void __launch_bounds__(NT, 2)
sp_kpass(const float* __restrict__ Kg, const float* __restrict__ omg, int ntiles) {
    extern __shared__ float sh[];
    uint32_t* Bff = (uint32_t*)sh;
    uint32_t* Aff = Bff + BFF_U32;
    float* hrow = (float*)(Aff + AFF_U32);   // 64
    float* cs   = hrow + 64;                 // 256
    unsigned* bmax = (unsigned*)(cs + NF);

    const int tid = threadIdx.x, wid = tid >> 5, lane = tid & 31;
    const int wr = wid >> 2, wc = wid & 3;

    load_B_h(omg, Bff, tid);
    if (tid < NF) cs[tid] = 0.f;
    if (tid == 0) *bmax = 0u;
    __syncthreads();

    float acc[2][8][4];
    for (int tile = blockIdx.x; tile < ntiles; tile += gridDim.x) {
        const size_t row0 = (size_t)tile * 64;
#pragma unroll
        for (int t = 0; t < 8; t++) {
            const int i = tid + t * NT;
            const int sr = i >> 5;                 // phys row 0..63
            float4 v = *(const float4*)(Kg + (row0 + sr) * KD + (lane << 2));
            float p = v.x * v.x + v.y * v.y + v.z * v.z + v.w * v.w;
#pragma unroll
            for (int o = 16; o; o >>= 1) p += __shfl_xor_sync(0xffffffffu, p, o);
            if (lane == 0) hrow[sr] = p * HC;
            frag_store(Aff, sr, lane, v);
        }
        __syncthreads();
        gemm_tile((const uint4*)Aff, (const uint4*)Bff, wr, wc, lane, acc);

        float colp[16];
#pragma unroll
        for (int t = 0; t < 16; t++) colp[t] = 0.f;
        float lmax = -INFINITY;
#pragma unroll
        for (int m = 0; m < 2; m++) {
            const int r1 = (wr * 2 + m) * 16 + (lane >> 2);
            const float hv1 = hrow[r1], hv2 = hrow[r1 + 8];
#pragma unroll
            for (int jn = 0; jn < 8; jn++)
#pragma unroll
                for (int cc = 0; cc < 2; cc++) {
                    const float u1 = acc[m][jn][cc], u2 = acc[m][jn][2 + cc];
                    lmax = fmaxf(lmax, fmaxf(u1, u2));
                    colp[jn * 2 + cc] += __expf(u1 - hv1) + __expf(u2 - hv2);
                }
        }
#pragma unroll
        for (int t = 0; t < 16; t++) {
            float s = colp[t];
            s += __shfl_xor_sync(0xffffffffu, s, 4);
            s += __shfl_xor_sync(0xffffffffu, s, 8);
            s += __shfl_xor_sync(0xffffffffu, s, 16);
            colp[t] = s;
        }
        if (lane < 4) {
#pragma unroll
            for (int t = 0; t < 16; t++)
                atomicAdd(&cs[wc * 64 + (t >> 1) * 8 + 2 * lane + (t & 1)], colp[t]);
        }
#pragma unroll
        for (int o = 16; o; o >>= 1)
            lmax = fmaxf(lmax, __shfl_xor_sync(0xffffffffu, lmax, o));
        if (lane == 0) atomicMax(bmax, f2u(lmax));
        __syncthreads();
    }
    if (tid < NF) atomicAdd(&g_sumKraw[tid], cs[tid]);
    if (tid == 0) atomicMax(&g_max_u, *bmax);
}

// ---------------- pass 2: interleaved Q/K tile (32 logical rows), scale V -------
__global__ void __launch_bounds__(NT, 2)
sp_final(const float* __restrict__ Qg, const float* __restrict__ Kg,
         const float* __restrict__ V, const float* __restrict__ omg,
         float* __restrict__ out, int ntiles) {
    extern __shared__ float sh[];
    uint32_t* Bff = (uint32_t*)sh;
    uint32_t* Aff = Bff + BFF_U32;
    float* hq    = (float*)(Aff + AFF_U32);  // 32
    float* hk    = hq + 32;                  // 32
    float* sKs   = hk + 32;                  // 256
    float* rmarr = sKs + NF;                 // 128
    float* red0  = rmarr + 128;              // 128
    float* red1  = red0 + 128;               // 128
    float* red2  = red1 + 128;               // 128
    float* red3  = red2 + 128;               // 128
    float* scal  = red3 + 128;               // 32
    float* ssum  = scal + 32;                // 1

    const int tid = threadIdx.x, wid = tid >> 5, lane = tid & 31;
    const int wr = wid >> 2, wc = wid & 3;
    const float gm = g_maxval;

    load_B_h(omg, Bff, tid);
    if (tid < NF) sKs[tid] = g_sumK[tid];
    __syncthreads();
    if (tid == 0) {
        float s = 0.f;
        for (int j = 0; j < NF; j++) s += sKs[j];
        *ssum = s;
    }
    __syncthreads();
    const float ssv = *ssum;

    float acc[2][8][4];
    for (int tile = blockIdx.x; tile < ntiles; tile += gridDim.x) {
        const size_t lr0 = (size_t)tile * 32;  // 32 logical rows per tile

        // interleaved load: 16-row block b holds 8 Q-rows then the same 8 K-rows
#pragma unroll
        for (int t = 0; t < 8; t++) {
            const int i = tid + t * NT;
            const int sr = i >> 5;                 // phys row 0..63
            const int b = sr >> 4, j = sr & 15;
            const int lr = b * 8 + (j & 7);        // logical row 0..31
            const float* src = ((j & 8) ? Kg : Qg) + (lr0 + lr) * KD + (lane << 2);
            float4 v = *(const float4*)src;
            float p = v.x * v.x + v.y * v.y + v.z * v.z + v.w * v.w;
#pragma unroll
            for (int o = 16; o; o >>= 1) p += __shfl_xor_sync(0xffffffffu, p, o);
            if (lane == 0) { if (j & 8) hk[lr] = p * HC; else hq[lr] = p * HC; }
            frag_store(Aff, sr, lane, v);
        }
        __syncthreads();

        gemm_tile((const uint4*)Aff, (const uint4*)Bff, wr, wc, lane, acc);
        // acc[m][jn][0,1] = U_Q(lrow,col), acc[m][jn][2,3] = U_K(lrow,col)
        // lrow = (wr*2+m)*8 + (lane>>2)

        // pass A: per-row max of U_Q (across this warp's 16 cols, then 4 warps)
#pragma unroll
        for (int m = 0; m < 2; m++) {
            const int lrow = (wr * 2 + m) * 8 + (lane >> 2);
            float mx = -INFINITY;
#pragma unroll
            for (int jn = 0; jn < 8; jn++) {
                mx = fmaxf(mx, acc[m][jn][0]);
                mx = fmaxf(mx, acc[m][jn][1]);
            }
            mx = grp_max(mx);
            if ((lane & 3) == 0) rmarr[lrow * 4 + wc] = mx;
        }
        __syncthreads();

        // pass B: W = sum eq*ek, S2 = sum eq, S3 = sum ek, T = sum eq*sK
#pragma unroll
        for (int m = 0; m < 2; m++) {
            const int lrow = (wr * 2 + m) * 8 + (lane >> 2);
            const float rmv = fmaxf(fmaxf(rmarr[lrow * 4], rmarr[lrow * 4 + 1]),
                                    fmaxf(rmarr[lrow * 4 + 2], rmarr[lrow * 4 + 3]));
            const float subq = hq[lrow] + rmv;
            const float subk = hk[lrow] + gm;
            float W = 0.f, S2 = 0.f, S3 = 0.f, T = 0.f;
#pragma unroll
            for (int jn = 0; jn < 8; jn++)
#pragma unroll
                for (int cc = 0; cc < 2; cc++) {
                    const int col = wc * 64 + jn * 8 + 2 * (lane & 3) + cc;
                    const float eq = __expf(acc[m][jn][cc] - subq);
                    const float ek = __expf(acc[m][jn][2 + cc] - subk);
                    W  = fmaf(eq, ek, W);
                    S2 += eq;
                    S3 += ek;
                    T  = fmaf(eq, sKs[col], T);
                }
            W = grp_sum(W); S2 = grp_sum(S2); S3 = grp_sum(S3); T = grp_sum(T);
            if ((lane & 3) == 0) {
                red0[lrow * 4 + wc] = W;  red1[lrow * 4 + wc] = S2;
                red2[lrow * 4 + wc] = S3; red3[lrow * 4 + wc] = T;
            }
        }
        __syncthreads();
        if (tid < 32) {
            const float W  = red0[tid * 4] + red0[tid * 4 + 1] + red0[tid * 4 + 2] + red0[tid * 4 + 3];
            const float S2 = red1[tid * 4] + red1[tid * 4 + 1] + red1[tid * 4 + 2] + red1[tid * 4 + 3];
            const float S3 = red2[tid * 4] + red2[tid * 4 + 1] + red2[tid * 4 + 2] + red2[tid * 4 + 3];
            const float T  = red3[tid * 4] + red3[tid * 4 + 1] + red3[tid * 4 + 2] + red3[tid * 4 + 3];
            const float w  = (W + 1e-4f * (S2 + S3) + 2.56e-6f) * (1.f / 256.f);
            const float nm = (T + 1e-4f * ssv) * 0.0625f + 1e-8f;
            scal[tid] = w / nm;
        }
        __syncthreads();

        // out = scal * V  (32 logical rows x 128 cols)
        const float4* Vg = (const float4*)(V + lr0 * KD);
        float4* Og = (float4*)(out + lr0 * KD);
#pragma unroll
        for (int t = 0; t < 4; t++) {
            const int i = tid + t * NT;
            const float s = scal[i >> 5];
            float4 v = Vg[i];
            v.x *= s; v.y *= s; v.z *= s; v.w *= s;
            Og[i] = v;
        }
        __syncthreads();
    }
}

// --------------------------------- host -----------------------------------------
extern "C" void kernel_launch(void* const* d_in, const int* in_sizes, int n_in,
                              void* d_out, int out_size) {
    const float* Q   = (const float*)d_in[0];
    const float* K   = (const float*)d_in[1];
    const float* V   = (const float*)d_in[2];
    const float* omg = (const float*)d_in[3];
    float* out = (float*)d_out;

    const int N = in_sizes[0] / KD;
    const int ntK = N / 64;    // 64 K-rows per kpass tile
    const int ntF = N / 32;    // 32 logical rows per final tile

    int dev = 0, sms = 148;
    cudaGetDevice(&dev);
    cudaDeviceGetAttribute(&sms, cudaDevAttrMultiProcessorCount, dev);
    const int gK = 2 * sms < ntK ? 2 * sms : ntK;
    const int gF = 2 * sms < ntF ? 2 * sms : ntF;

    const size_t base = (size_t)(BFF_U32 + AFF_U32) * 4;
    const size_t smK = base + (64 + NF + 4) * sizeof(float);
    const size_t smF = base + (32 * 2 + NF + 128 * 5 + 32 + 8) * sizeof(float);
    cudaFuncSetAttribute(sp_kpass, cudaFuncAttributeMaxDynamicSharedMemorySize, (int)smK);
    cudaFuncSetAttribute(sp_final, cudaFuncAttributeMaxDynamicSharedMemorySize, (int)smF);

    sp_init<<<1, NF>>>();
    sp_kpass<<<gK, NT, smK>>>(K, omg, ntK);
    sp_finalize<<<1, NF>>>((float)N * 1e-4f);
    sp_final<<<gF, NT, smF>>>(Q, K, V, omg, out, ntF);
}

// round 9
// speedup vs baseline: 1.3496x; 1.0908x over previous
#include <cuda_runtime.h>
#include <cuda_fp16.h>
#include <math.h>
#include <stdint.h>

#define NT     256
#define NF     256
#define KD     128
#define NMAX   262144

#define INVD4  0.2973017787506803f    // 128^(-1/4)
#define HC     0.04419417382415922f   // 1/(2*sqrt(128))

#define BFF_U32 16384                 // B fragments (fp16): 64 KB
#define AFF_U32 4096                  // A fragments (fp16, 64 phys rows): 16 KB

// ---------------- globals -------------------------------------------------------
static __device__ unsigned g_max_u;
static __device__ float    g_maxval;
static __device__ float    g_sumKraw[NF];
static __device__ float    g_sumK[NF];
static __device__ float    g_srow[NMAX];                 // per-row max of raw U_K
static __device__ __half2  g_E2[(size_t)NMAX * 128];     // exp(U_K - h - srow), frag order

__device__ __forceinline__ unsigned f2u(float f) {
    unsigned b = __float_as_uint(f);
    return (b & 0x80000000u) ? ~b : (b | 0x80000000u);
}
__device__ __forceinline__ float u2f(unsigned u) {
    return (u & 0x80000000u) ? __uint_as_float(u ^ 0x80000000u) : __uint_as_float(~u);
}

__global__ void sp_init() {
    if (threadIdx.x == 0) g_max_u = 0u;
    g_sumKraw[threadIdx.x] = 0.f;
}
__global__ void sp_finalize(float neps) {
    const float gmax = u2f(g_max_u);
    if (threadIdx.x == 0) g_maxval = gmax;
    g_sumK[threadIdx.x] = (g_sumKraw[threadIdx.x] * expf(-gmax) + neps) * 0.0625f;
}

// ---------------- fp16 mma machinery --------------------------------------------
__device__ __forceinline__ void mma_f16(float* d, const uint4& a, uint32_t b0, uint32_t b1) {
    asm volatile(
        "mma.sync.aligned.m16n8k16.row.col.f32.f16.f16.f32 "
        "{%0,%1,%2,%3}, {%4,%5,%6,%7}, {%8,%9}, {%0,%1,%2,%3};\n"
        : "+f"(d[0]), "+f"(d[1]), "+f"(d[2]), "+f"(d[3])
        : "r"(a.x), "r"(a.y), "r"(a.z), "r"(a.w), "r"(b0), "r"(b1));
}

__device__ __forceinline__ void load_B_h(const float* __restrict__ omg,
                                         uint32_t* __restrict__ Bff, int tid) {
    __half* Bh = (__half*)Bff;
    for (int i = tid; i < KD * NF; i += NT) {
        const int k = i >> 8, n = i & 255;
        const __half hv = __float2half(omg[i] * INVD4);
        const int np = n >> 3, npair = np >> 1, ks = k >> 4;
        const int lane = ((n & 7) << 2) | ((k & 7) >> 1);
        const int slot = ((np & 1) << 1) | ((k >> 3) & 1);
        const int u32idx = ((npair * 8 + ks) * 32 + lane) * 4 + slot;
        Bh[u32idx * 2 + (k & 1)] = hv;
    }
}

__device__ __forceinline__ void frag_store(uint32_t* __restrict__ Aff, int sr, int lane,
                                           const float4& v) {
    __half2 h01 = __floats2half2_rn(v.x, v.y);
    __half2 h23 = __floats2half2_rn(v.z, v.w);
    const int k0 = lane << 2;
    const int mi = sr >> 4, rlo = sr & 15, ks = k0 >> 4;
    const int reg = ((rlo >> 3) & 1) | (((k0 >> 3) & 1) << 1);
    const int ls  = ((rlo & 7) << 2) | ((k0 >> 1) & 3);
    uint32_t* base = Aff + (unsigned)((mi * 8 + ks) * 32) * 4 + reg;
    base[ls * 4]       = *(uint32_t*)&h01;
    base[(ls + 1) * 4] = *(uint32_t*)&h23;
}

// 64x256x128 GEMM, 8 warps, warp (wr,wc) owns 32 phys rows x 64 cols
__device__ __forceinline__ void gemm_tile(const uint4* __restrict__ Aff4,
                                          const uint4* __restrict__ Bff4,
                                          int wr, int wc, int lane, float acc[2][8][4]) {
#pragma unroll
    for (int i = 0; i < 2; i++)
#pragma unroll
        for (int j = 0; j < 8; j++)
#pragma unroll
            for (int c = 0; c < 4; c++) acc[i][j][c] = 0.f;
#pragma unroll
    for (int ks = 0; ks < 8; ks++) {
        uint4 a0 = Aff4[((wr * 2) * 8 + ks) * 32 + lane];
        uint4 a1 = Aff4[((wr * 2 + 1) * 8 + ks) * 32 + lane];
#pragma unroll
        for (int p = 0; p < 4; p++) {
            uint4 bv = Bff4[((wc * 4 + p) * 8 + ks) * 32 + lane];
            mma_f16(acc[0][2 * p],     a0, bv.x, bv.y);
            mma_f16(acc[0][2 * p + 1], a0, bv.z, bv.w);
            mma_f16(acc[1][2 * p],     a1, bv.x, bv.y);
            mma_f16(acc[1][2 * p + 1], a1, bv.z, bv.w);
        }
    }
}

__device__ __forceinline__ float grp_sum(float v) {
    v += __shfl_xor_sync(0xffffffffu, v, 1);
    v += __shfl_xor_sync(0xffffffffu, v, 2);
    return v;
}
__device__ __forceinline__ float grp_max(float v) {
    v = fmaxf(v, __shfl_xor_sync(0xffffffffu, v, 1));
    v = fmaxf(v, __shfl_xor_sync(0xffffffffu, v, 2));
    return v;
}

// ---------------- pass 1: U_K -> gmax, colsums, E' cache ------------------------
__global__ void __launch_bounds__(NT, 2)
sp_kpass(const float* __restrict__ Kg, const float* __restrict__ omg, int ntiles) {
    extern __shared__ float sh[];
    uint32_t* Bff = (uint32_t*)sh;
    uint32_t* Aff = Bff + BFF_U32;
    float* hrow  = (float*)(Aff + AFF_U32);  // 64
    float* cs    = hrow + 64;                // 256
    float* rmarr = cs + NF;                  // 256
    unsigned* bmax = (unsigned*)(rmarr + 256);

    const int tid = threadIdx.x, wid = tid >> 5, lane = tid & 31;
    const int wr = wid >> 2, wc = wid & 3;

    load_B_h(omg, Bff, tid);
    if (tid < NF) cs[tid] = 0.f;
    if (tid == 0) *bmax = 0u;
    __syncthreads();

    float acc[2][8][4];
    for (int tile = blockIdx.x; tile < ntiles; tile += gridDim.x) {
        const size_t row0 = (size_t)tile * 64;
#pragma unroll
        for (int t = 0; t < 8; t++) {
            const int i = tid + t * NT;
            const int sr = i >> 5;
            float4 v = *(const float4*)(Kg + (row0 + sr) * KD + (lane << 2));
            float p = v.x * v.x + v.y * v.y + v.z * v.z + v.w * v.w;
#pragma unroll
            for (int o = 16; o; o >>= 1) p += __shfl_xor_sync(0xffffffffu, p, o);
            if (lane == 0) hrow[sr] = p * HC;
            frag_store(Aff, sr, lane, v);
        }
        __syncthreads();
        gemm_tile((const uint4*)Aff, (const uint4*)Bff, wr, wc, lane, acc);

        // pass A: per-row max of raw U_K
        float lmax = -INFINITY;
#pragma unroll
        for (int m = 0; m < 2; m++) {
            const int r1 = (wr * 2 + m) * 16 + (lane >> 2);
            float mx1 = -INFINITY, mx2 = -INFINITY;
#pragma unroll
            for (int jn = 0; jn < 8; jn++) {
                mx1 = fmaxf(mx1, fmaxf(acc[m][jn][0], acc[m][jn][1]));
                mx2 = fmaxf(mx2, fmaxf(acc[m][jn][2], acc[m][jn][3]));
            }
            mx1 = grp_max(mx1); mx2 = grp_max(mx2);
            lmax = fmaxf(lmax, fmaxf(mx1, mx2));
            if ((lane & 3) == 0) {
                rmarr[r1 * 4 + wc] = mx1;
                rmarr[(r1 + 8) * 4 + wc] = mx2;
            }
        }
#pragma unroll
        for (int o = 16; o; o >>= 1)
            lmax = fmaxf(lmax, __shfl_xor_sync(0xffffffffu, lmax, o));
        if (lane == 0) atomicMax(bmax, f2u(lmax));
        __syncthreads();

        // pass B: E' = exp(u - h - srow), colsums += E'*exp(srow), store E' + srow
        float colp[16];
#pragma unroll
        for (int t = 0; t < 16; t++) colp[t] = 0.f;
#pragma unroll
        for (int m = 0; m < 2; m++)
#pragma unroll
            for (int half = 0; half < 2; half++) {
                const int row = (wr * 2 + m) * 16 + (lane >> 2) + 8 * half;
                const float s_r = fmaxf(fmaxf(rmarr[row * 4], rmarr[row * 4 + 1]),
                                        fmaxf(rmarr[row * 4 + 2], rmarr[row * 4 + 3]));
                const float hv = hrow[row];
                const float erm = __expf(s_r);
                const unsigned ub =
                    ((((unsigned)tile * 8u + wid) * 2u + m) * 2u + half) * 256u + lane;
#pragma unroll
                for (int jn = 0; jn < 8; jn++) {
                    const float E0 = __expf(acc[m][jn][half * 2]     - hv - s_r);
                    const float E1 = __expf(acc[m][jn][half * 2 + 1] - hv - s_r);
                    colp[jn * 2]     += E0 * erm;
                    colp[jn * 2 + 1] += E1 * erm;
                    g_E2[ub + jn * 32u] = __floats2half2_rn(E0, E1);
                }
                if ((lane & 3) == 0) g_srow[row0 + row] = s_r;
            }
#pragma unroll
        for (int t = 0; t < 16; t++) {
            float s = colp[t];
            s += __shfl_xor_sync(0xffffffffu, s, 4);
            s += __shfl_xor_sync(0xffffffffu, s, 8);
            s += __shfl_xor_sync(0xffffffffu, s, 16);
            colp[t] = s;
        }
        if (lane < 4) {
#pragma unroll
            for (int t = 0; t < 16; t++)
                atomicAdd(&cs[wc * 64 + (t >> 1) * 8 + 2 * lane + (t & 1)], colp[t]);
        }
        __syncthreads();
    }
    if (tid < NF) atomicAdd(&g_sumKraw[tid], cs[tid]);
    if (tid == 0) atomicMax(&g_max_u, *bmax);
}

// ---------------- pass 2: Q GEMM + cached ek, scale V ---------------------------
__global__ void __launch_bounds__(NT, 2)
sp_final(const float* __restrict__ Qg, const float* __restrict__ V,
         const float* __restrict__ omg, float* __restrict__ out, int ntiles) {
    extern __shared__ float sh[];
    uint32_t* Bff = (uint32_t*)sh;
    uint32_t* Aff = Bff + BFF_U32;
    float* hq    = (float*)(Aff + AFF_U32);  // 64
    float* sKs   = hq + 64;                  // 256
    float* rmarr = sKs + NF;                 // 256
    float* red0  = rmarr + 256;              // 256
    float* red1  = red0 + 256;               // 256
    float* red2  = red1 + 256;               // 256
    float* red3  = red2 + 256;               // 256
    float* scal  = red3 + 256;               // 64
    float* ssum  = scal + 64;                // 1

    const int tid = threadIdx.x, wid = tid >> 5, lane = tid & 31;
    const int wr = wid >> 2, wc = wid & 3;
    const float gm = g_maxval;

    load_B_h(omg, Bff, tid);
    if (tid < NF) sKs[tid] = g_sumK[tid];
    __syncthreads();
    if (tid == 0) {
        float s = 0.f;
        for (int j = 0; j < NF; j++) s += sKs[j];
        *ssum = s;
    }
    __syncthreads();
    const float ssv = *ssum;

    float acc[2][8][4];
    for (int tile = blockIdx.x; tile < ntiles; tile += gridDim.x) {
        const size_t row0 = (size_t)tile * 64;
#pragma unroll
        for (int t = 0; t < 8; t++) {
            const int i = tid + t * NT;
            const int sr = i >> 5;
            float4 v = *(const float4*)(Qg + (row0 + sr) * KD + (lane << 2));
            float p = v.x * v.x + v.y * v.y + v.z * v.z + v.w * v.w;
#pragma unroll
            for (int o = 16; o; o >>= 1) p += __shfl_xor_sync(0xffffffffu, p, o);
            if (lane == 0) hq[sr] = p * HC;
            frag_store(Aff, sr, lane, v);
        }
        __syncthreads();
        gemm_tile((const uint4*)Aff, (const uint4*)Bff, wr, wc, lane, acc);

        // pass A: per-row max of raw U_Q
#pragma unroll
        for (int m = 0; m < 2; m++) {
            const int r1 = (wr * 2 + m) * 16 + (lane >> 2);
            float mx1 = -INFINITY, mx2 = -INFINITY;
#pragma unroll
            for (int jn = 0; jn < 8; jn++) {
                mx1 = fmaxf(mx1, fmaxf(acc[m][jn][0], acc[m][jn][1]));
                mx2 = fmaxf(mx2, fmaxf(acc[m][jn][2], acc[m][jn][3]));
            }
            mx1 = grp_max(mx1); mx2 = grp_max(mx2);
            if ((lane & 3) == 0) {
                rmarr[r1 * 4 + wc] = mx1;
                rmarr[(r1 + 8) * 4 + wc] = mx2;
            }
        }
        __syncthreads();

        // pass B: W, S2, S3, T using cached ek
#pragma unroll
        for (int m = 0; m < 2; m++)
#pragma unroll
            for (int half = 0; half < 2; half++) {
                const int row = (wr * 2 + m) * 16 + (lane >> 2) + 8 * half;
                const float rmv = fmaxf(fmaxf(rmarr[row * 4], rmarr[row * 4 + 1]),
                                        fmaxf(rmarr[row * 4 + 2], rmarr[row * 4 + 3]));
                const float subq = hq[row] + rmv;
                const float eksc = __expf(g_srow[row0 + row] - gm);
                const unsigned ub =
                    ((((unsigned)tile * 8u + wid) * 2u + m) * 2u + half) * 256u + lane;
                float W = 0.f, S2 = 0.f, S3 = 0.f, T = 0.f;
#pragma unroll
                for (int jn = 0; jn < 8; jn++) {
                    const __half2 e2 = g_E2[ub + jn * 32u];
                    const float2 ef = __half22float2(e2);
                    const float ek0 = ef.x * eksc, ek1 = ef.y * eksc;
                    const float eq0 = __expf(acc[m][jn][half * 2]     - subq);
                    const float eq1 = __expf(acc[m][jn][half * 2 + 1] - subq);
                    const int col0 = wc * 64 + jn * 8 + 2 * (lane & 3);
                    W  = fmaf(eq0, ek0, W);
                    W  = fmaf(eq1, ek1, W);
                    S2 += eq0 + eq1;
                    S3 += ek0 + ek1;
                    T  = fmaf(eq0, sKs[col0], T);
                    T  = fmaf(eq1, sKs[col0 + 1], T);
                }
                W = grp_sum(W); S2 = grp_sum(S2); S3 = grp_sum(S3); T = grp_sum(T);
                if ((lane & 3) == 0) {
                    red0[row * 4 + wc] = W;  red1[row * 4 + wc] = S2;
                    red2[row * 4 + wc] = S3; red3[row * 4 + wc] = T;
                }
            }
        __syncthreads();
        if (tid < 64) {
            const float W  = red0[tid * 4] + red0[tid * 4 + 1] + red0[tid * 4 + 2] + red0[tid * 4 + 3];
            const float S2 = red1[tid * 4] + red1[tid * 4 + 1] + red1[tid * 4 + 2] + red1[tid * 4 + 3];
            const float S3 = red2[tid * 4] + red2[tid * 4 + 1] + red2[tid * 4 + 2] + red2[tid * 4 + 3];
            const float T  = red3[tid * 4] + red3[tid * 4 + 1] + red3[tid * 4 + 2] + red3[tid * 4 + 3];
            const float w  = (W + 1e-4f * (S2 + S3) + 2.56e-6f) * (1.f / 256.f);
            const float nm = (T + 1e-4f * ssv) * 0.0625f + 1e-8f;
            scal[tid] = w / nm;
        }
        __syncthreads();

        const float4* Vg = (const float4*)(V + row0 * KD);
        float4* Og = (float4*)(out + row0 * KD);
#pragma unroll
        for (int t = 0; t < 8; t++) {
            const int i = tid + t * NT;
            const float s = scal[i >> 5];
            float4 v = Vg[i];
            v.x *= s; v.y *= s; v.z *= s; v.w *= s;
            Og[i] = v;
        }
        __syncthreads();
    }
}

// --------------------------------- host -----------------------------------------
extern "C" void kernel_launch(void* const* d_in, const int* in_sizes, int n_in,
                              void* d_out, int out_size) {
    const float* Q   = (const float*)d_in[0];
    const float* K   = (const float*)d_in[1];
    const float* V   = (const float*)d_in[2];
    const float* omg = (const float*)d_in[3];
    float* out = (float*)d_out;

    const int N = in_sizes[0] / KD;
    const int ntiles = N / 64;

    int dev = 0, sms = 148;
    cudaGetDevice(&dev);
    cudaDeviceGetAttribute(&sms, cudaDevAttrMultiProcessorCount, dev);
    const int grid = 2 * sms < ntiles ? 2 * sms : ntiles;

    const size_t base = (size_t)(BFF_U32 + AFF_U32) * 4;
    const size_t smK = base + (64 + NF + 256 + 4) * sizeof(float);
    const size_t smF = base + (64 + NF + 256 + 256 * 4 + 64 + 8) * sizeof(float);
    cudaFuncSetAttribute(sp_kpass, cudaFuncAttributeMaxDynamicSharedMemorySize, (int)smK);
    cudaFuncSetAttribute(sp_final, cudaFuncAttributeMaxDynamicSharedMemorySize, (int)smF);

    sp_init<<<1, NF>>>();
    sp_kpass<<<grid, NT, smK>>>(K, omg, ntiles);
    sp_finalize<<<1, NF>>>((float)N * 1e-4f);
    sp_final<<<grid, NT, smF>>>(Q, V, omg, out, ntiles);
}

// round 10
// speedup vs baseline: 1.3703x; 1.0154x over previous
#include <cuda_runtime.h>
#include <cuda_fp16.h>
#include <math.h>
#include <stdint.h>

#define NT     256
#define NF     256
#define KD     128
#define NMAX   262144

#define INVD4  0.2973017787506803f    // 128^(-1/4)
#define HC     0.04419417382415922f   // 1/(2*sqrt(128))

#define BFF_U32 16384                 // B fragments (fp16): 64 KB
#define AFF_U32 4096                  // A fragments (fp16, 64 phys rows): 16 KB
#define BUF_U32 8192                  // final: A-frags/chunk1 + chunk0 overlay: 32 KB

// ---------------- globals -------------------------------------------------------
static __device__ unsigned g_max_u;
static __device__ float    g_maxval;
static __device__ float    g_sumKraw[NF];
static __device__ float    g_sumK[NF];
static __device__ float    g_srow[NMAX];                 // per-row max of raw U_K
// E' = exp(U_K - h - srow), m-chunked frag order:
// idx = ((tile*2 + m)*8 + wid)*512 + half*256 + jn*32 + lane
static __device__ __half2  g_E2[(size_t)NMAX * 128];

__device__ __forceinline__ unsigned f2u(float f) {
    unsigned b = __float_as_uint(f);
    return (b & 0x80000000u) ? ~b : (b | 0x80000000u);
}
__device__ __forceinline__ float u2f(unsigned u) {
    return (u & 0x80000000u) ? __uint_as_float(u ^ 0x80000000u) : __uint_as_float(~u);
}

__global__ void sp_init() {
    if (threadIdx.x == 0) g_max_u = 0u;
    g_sumKraw[threadIdx.x] = 0.f;
}
__global__ void sp_finalize(float neps) {
    const float gmax = u2f(g_max_u);
    if (threadIdx.x == 0) g_maxval = gmax;
    g_sumK[threadIdx.x] = (g_sumKraw[threadIdx.x] * expf(-gmax) + neps) * 0.0625f;
}

// ---------------- low-level helpers ---------------------------------------------
__device__ __forceinline__ uint32_t smem_u32(const void* p) {
    uint32_t a;
    asm("{ .reg .u64 t; cvta.to.shared.u64 t, %1; cvt.u32.u64 %0, t; }" : "=r"(a) : "l"(p));
    return a;
}
__device__ __forceinline__ void cp_async16(uint32_t dst, const void* src) {
    asm volatile("cp.async.cg.shared.global [%0], [%1], 16;" :: "r"(dst), "l"(src));
}
#define CP_COMMIT() asm volatile("cp.async.commit_group;" ::: "memory")
#define CP_WAIT1()  asm volatile("cp.async.wait_group 1;" ::: "memory")
#define CP_WAIT0()  asm volatile("cp.async.wait_group 0;" ::: "memory")

__device__ __forceinline__ void mma_f16(float* d, const uint4& a, uint32_t b0, uint32_t b1) {
    asm volatile(
        "mma.sync.aligned.m16n8k16.row.col.f32.f16.f16.f32 "
        "{%0,%1,%2,%3}, {%4,%5,%6,%7}, {%8,%9}, {%0,%1,%2,%3};\n"
        : "+f"(d[0]), "+f"(d[1]), "+f"(d[2]), "+f"(d[3])
        : "r"(a.x), "r"(a.y), "r"(a.z), "r"(a.w), "r"(b0), "r"(b1));
}

__device__ __forceinline__ void load_B_h(const float* __restrict__ omg,
                                         uint32_t* __restrict__ Bff, int tid) {
    __half* Bh = (__half*)Bff;
    for (int i = tid; i < KD * NF; i += NT) {
        const int k = i >> 8, n = i & 255;
        const __half hv = __float2half(omg[i] * INVD4);
        const int np = n >> 3, npair = np >> 1, ks = k >> 4;
        const int lane = ((n & 7) << 2) | ((k & 7) >> 1);
        const int slot = ((np & 1) << 1) | ((k >> 3) & 1);
        const int u32idx = ((npair * 8 + ks) * 32 + lane) * 4 + slot;
        Bh[u32idx * 2 + (k & 1)] = hv;
    }
}

__device__ __forceinline__ void frag_store(uint32_t* __restrict__ Aff, int sr, int lane,
                                           const float4& v) {
    __half2 h01 = __floats2half2_rn(v.x, v.y);
    __half2 h23 = __floats2half2_rn(v.z, v.w);
    const int k0 = lane << 2;
    const int mi = sr >> 4, rlo = sr & 15, ks = k0 >> 4;
    const int reg = ((rlo >> 3) & 1) | (((k0 >> 3) & 1) << 1);
    const int ls  = ((rlo & 7) << 2) | ((k0 >> 1) & 3);
    uint32_t* base = Aff + (unsigned)((mi * 8 + ks) * 32) * 4 + reg;
    base[ls * 4]       = *(uint32_t*)&h01;
    base[(ls + 1) * 4] = *(uint32_t*)&h23;
}

// 64x256x128 GEMM, 8 warps, warp (wr,wc) owns 32 phys rows x 64 cols
__device__ __forceinline__ void gemm_tile(const uint4* __restrict__ Aff4,
                                          const uint4* __restrict__ Bff4,
                                          int wr, int wc, int lane, float acc[2][8][4]) {
#pragma unroll
    for (int i = 0; i < 2; i++)
#pragma unroll
        for (int j = 0; j < 8; j++)
#pragma unroll
            for (int c = 0; c < 4; c++) acc[i][j][c] = 0.f;
#pragma unroll
    for (int ks = 0; ks < 8; ks++) {
        uint4 a0 = Aff4[((wr * 2) * 8 + ks) * 32 + lane];
        uint4 a1 = Aff4[((wr * 2 + 1) * 8 + ks) * 32 + lane];
#pragma unroll
        for (int p = 0; p < 4; p++) {
            uint4 bv = Bff4[((wc * 4 + p) * 8 + ks) * 32 + lane];
            mma_f16(acc[0][2 * p],     a0, bv.x, bv.y);
            mma_f16(acc[0][2 * p + 1], a0, bv.z, bv.w);
            mma_f16(acc[1][2 * p],     a1, bv.x, bv.y);
            mma_f16(acc[1][2 * p + 1], a1, bv.z, bv.w);
        }
    }
}

__device__ __forceinline__ float grp_sum(float v) {
    v += __shfl_xor_sync(0xffffffffu, v, 1);
    v += __shfl_xor_sync(0xffffffffu, v, 2);
    return v;
}
__device__ __forceinline__ float grp_max(float v) {
    v = fmaxf(v, __shfl_xor_sync(0xffffffffu, v, 1));
    v = fmaxf(v, __shfl_xor_sync(0xffffffffu, v, 2));
    return v;
}

// ---------------- pass 1: U_K -> gmax, colsums, E' cache ------------------------
__global__ void __launch_bounds__(NT, 2)
sp_kpass(const float* __restrict__ Kg, const float* __restrict__ omg, int ntiles) {
    extern __shared__ float sh[];
    uint32_t* Bff = (uint32_t*)sh;
    uint32_t* Aff = Bff + BFF_U32;
    float* hrow  = (float*)(Aff + AFF_U32);  // 64
    float* cs    = hrow + 64;                // 256
    float* rmarr = cs + NF;                  // 256
    unsigned* bmax = (unsigned*)(rmarr + 256);

    const int tid = threadIdx.x, wid = tid >> 5, lane = tid & 31;
    const int wr = wid >> 2, wc = wid & 3;

    load_B_h(omg, Bff, tid);
    if (tid < NF) cs[tid] = 0.f;
    if (tid == 0) *bmax = 0u;
    __syncthreads();

    float acc[2][8][4];
    for (int tile = blockIdx.x; tile < ntiles; tile += gridDim.x) {
        const size_t row0 = (size_t)tile * 64;
#pragma unroll
        for (int t = 0; t < 8; t++) {
            const int i = tid + t * NT;
            const int sr = i >> 5;
            float4 v = *(const float4*)(Kg + (row0 + sr) * KD + (lane << 2));
            float p = v.x * v.x + v.y * v.y + v.z * v.z + v.w * v.w;
#pragma unroll
            for (int o = 16; o; o >>= 1) p += __shfl_xor_sync(0xffffffffu, p, o);
            if (lane == 0) hrow[sr] = p * HC;
            frag_store(Aff, sr, lane, v);
        }
        __syncthreads();
        gemm_tile((const uint4*)Aff, (const uint4*)Bff, wr, wc, lane, acc);

        // pass A: per-row max of raw U_K
        float lmax = -INFINITY;
#pragma unroll
        for (int m = 0; m < 2; m++) {
            const int r1 = (wr * 2 + m) * 16 + (lane >> 2);
            float mx1 = -INFINITY, mx2 = -INFINITY;
#pragma unroll
            for (int jn = 0; jn < 8; jn++) {
                mx1 = fmaxf(mx1, fmaxf(acc[m][jn][0], acc[m][jn][1]));
                mx2 = fmaxf(mx2, fmaxf(acc[m][jn][2], acc[m][jn][3]));
            }
            mx1 = grp_max(mx1); mx2 = grp_max(mx2);
            lmax = fmaxf(lmax, fmaxf(mx1, mx2));
            if ((lane & 3) == 0) {
                rmarr[r1 * 4 + wc] = mx1;
                rmarr[(r1 + 8) * 4 + wc] = mx2;
            }
        }
#pragma unroll
        for (int o = 16; o; o >>= 1)
            lmax = fmaxf(lmax, __shfl_xor_sync(0xffffffffu, lmax, o));
        if (lane == 0) atomicMax(bmax, f2u(lmax));
        __syncthreads();

        // pass B: E' = exp(u - h - srow), colsums += E'*exp(srow), store E' + srow
        float colp[16];
#pragma unroll
        for (int t = 0; t < 16; t++) colp[t] = 0.f;
#pragma unroll
        for (int m = 0; m < 2; m++)
#pragma unroll
            for (int half = 0; half < 2; half++) {
                const int row = (wr * 2 + m) * 16 + (lane >> 2) + 8 * half;
                const float s_r = fmaxf(fmaxf(rmarr[row * 4], rmarr[row * 4 + 1]),
                                        fmaxf(rmarr[row * 4 + 2], rmarr[row * 4 + 3]));
                const float hv = hrow[row];
                const float erm = __expf(s_r);
                const size_t ub =
                    (((size_t)tile * 2 + m) * 8 + wid) * 512 + half * 256 + lane;
#pragma unroll
                for (int jn = 0; jn < 8; jn++) {
                    const float E0 = __expf(acc[m][jn][half * 2]     - hv - s_r);
                    const float E1 = __expf(acc[m][jn][half * 2 + 1] - hv - s_r);
                    colp[jn * 2]     += E0 * erm;
                    colp[jn * 2 + 1] += E1 * erm;
                    g_E2[ub + jn * 32u] = __floats2half2_rn(E0, E1);
                }
                if ((lane & 3) == 0) g_srow[row0 + row] = s_r;
            }
#pragma unroll
        for (int t = 0; t < 16; t++) {
            float s = colp[t];
            s += __shfl_xor_sync(0xffffffffu, s, 4);
            s += __shfl_xor_sync(0xffffffffu, s, 8);
            s += __shfl_xor_sync(0xffffffffu, s, 16);
            colp[t] = s;
        }
        if (lane < 4) {
#pragma unroll
            for (int t = 0; t < 16; t++)
                atomicAdd(&cs[wc * 64 + (t >> 1) * 8 + 2 * lane + (t & 1)], colp[t]);
        }
        __syncthreads();
    }
    if (tid < NF) atomicAdd(&g_sumKraw[tid], cs[tid]);
    if (tid == 0) atomicMax(&g_max_u, *bmax);
}

// ---------------- pass 2: Q GEMM + smem-staged ek, scale V ----------------------
__device__ __forceinline__ void passB_m(
    int m, const __half2* __restrict__ chunk, const float acc[2][8][4],
    int wid, int wr, int wc, int lane, float gm,
    const float* __restrict__ hq, const float* __restrict__ srw,
    const float* __restrict__ sKs, const float* __restrict__ rmarr,
    float* __restrict__ red0, float* __restrict__ red1,
    float* __restrict__ red2, float* __restrict__ red3) {
#pragma unroll
    for (int half = 0; half < 2; half++) {
        const int row = (wr * 2 + m) * 16 + (lane >> 2) + 8 * half;
        const float rmv = fmaxf(fmaxf(rmarr[row * 4], rmarr[row * 4 + 1]),
                                fmaxf(rmarr[row * 4 + 2], rmarr[row * 4 + 3]));
        const float subq = hq[row] + rmv;
        const float eksc = __expf(srw[row] - gm);
        const int cb = wid * 512 + half * 256 + lane;
        float W = 0.f, S2 = 0.f, S3 = 0.f, T = 0.f;
#pragma unroll
        for (int jn = 0; jn < 8; jn++) {
            const float2 ef = __half22float2(chunk[cb + jn * 32]);
            const float ek0 = ef.x * eksc, ek1 = ef.y * eksc;
            const float eq0 = __expf(acc[m][jn][half * 2]     - subq);
            const float eq1 = __expf(acc[m][jn][half * 2 + 1] - subq);
            const int col0 = wc * 64 + jn * 8 + 2 * (lane & 3);
            W  = fmaf(eq0, ek0, W);
            W  = fmaf(eq1, ek1, W);
            S2 += eq0 + eq1;
            S3 += ek0 + ek1;
            T  = fmaf(eq0, sKs[col0], T);
            T  = fmaf(eq1, sKs[col0 + 1], T);
        }
        W = grp_sum(W); S2 = grp_sum(S2); S3 = grp_sum(S3); T = grp_sum(T);
        if ((lane & 3) == 0) {
            red0[row * 4 + wc] = W;  red1[row * 4 + wc] = S2;
            red2[row * 4 + wc] = S3; red3[row * 4 + wc] = T;
        }
    }
}

__global__ void __launch_bounds__(NT, 2)
sp_final(const float* __restrict__ Qg, const float* __restrict__ V,
         const float* __restrict__ omg, float* __restrict__ out, int ntiles) {
    extern __shared__ float sh[];
    uint32_t* Bff = (uint32_t*)sh;
    uint32_t* buf = Bff + BFF_U32;           // 32 KB: [0:16K)=A-frags/chunk1, [16K:32K)=chunk0
    float* hq    = (float*)(buf + BUF_U32);  // 64
    float* sKs   = hq + 64;                  // 256
    float* srw   = sKs + NF;                 // 64
    float* rmarr = srw + 64;                 // 256
    float* red0  = rmarr + 256;              // 256
    float* red1  = red0 + 256;               // 256
    float* red2  = red1 + 256;               // 256
    float* red3  = red2 + 256;               // 256
    float* scal  = red3 + 256;               // 64
    float* ssum  = scal + 64;                // 1

    const int tid = threadIdx.x, wid = tid >> 5, lane = tid & 31;
    const int wr = wid >> 2, wc = wid & 3;
    const float gm = g_maxval;
    const uint32_t buf0 = smem_u32(buf);
    const uint32_t buf1 = buf0 + 16384;
    const uint32_t srw32 = smem_u32(srw);
    const __half2* chunk0 = (const __half2*)(buf + 4096);
    const __half2* chunk1 = (const __half2*)buf;

    load_B_h(omg, Bff, tid);
    if (tid < NF) sKs[tid] = g_sumK[tid];
    __syncthreads();
    if (tid == 0) {
        float s = 0.f;
        for (int j = 0; j < NF; j++) s += sKs[j];
        *ssum = s;
    }
    __syncthreads();
    const float ssv = *ssum;

    float acc[2][8][4];
    for (int tile = blockIdx.x; tile < ntiles; tile += gridDim.x) {
        const size_t row0 = (size_t)tile * 64;

        // (a) A frags + h; chunk0 + srow DMA
#pragma unroll
        for (int t = 0; t < 8; t++) {
            const int i = tid + t * NT;
            const int sr = i >> 5;
            float4 v = *(const float4*)(Qg + (row0 + sr) * KD + (lane << 2));
            float p = v.x * v.x + v.y * v.y + v.z * v.z + v.w * v.w;
#pragma unroll
            for (int o = 16; o; o >>= 1) p += __shfl_xor_sync(0xffffffffu, p, o);
            if (lane == 0) hq[sr] = p * HC;
            frag_store(buf, sr, lane, v);
        }
        {
            const char* src0 = (const char*)(g_E2 + ((size_t)tile * 2) * 4096);
#pragma unroll
            for (int c = 0; c < 4; c++)
                cp_async16(buf1 + (unsigned)(tid + c * NT) * 16, src0 + (size_t)(tid + c * NT) * 16);
            if (tid < 16) cp_async16(srw32 + tid * 16, g_srow + row0 + tid * 4);
        }
        CP_COMMIT();
        __syncthreads();                                       // (b)

        gemm_tile((const uint4*)buf, (const uint4*)Bff, wr, wc, lane, acc);
        __syncthreads();                                       // (d) A dead

        {
            const char* src1 = (const char*)(g_E2 + ((size_t)tile * 2 + 1) * 4096);
#pragma unroll
            for (int c = 0; c < 4; c++)
                cp_async16(buf0 + (unsigned)(tid + c * NT) * 16, src1 + (size_t)(tid + c * NT) * 16);
        }
        CP_COMMIT();

        // pass A: per-row max of raw U_Q
#pragma unroll
        for (int m = 0; m < 2; m++) {
            const int r1 = (wr * 2 + m) * 16 + (lane >> 2);
            float mx1 = -INFINITY, mx2 = -INFINITY;
#pragma unroll
            for (int jn = 0; jn < 8; jn++) {
                mx1 = fmaxf(mx1, fmaxf(acc[m][jn][0], acc[m][jn][1]));
                mx2 = fmaxf(mx2, fmaxf(acc[m][jn][2], acc[m][jn][3]));
            }
            mx1 = grp_max(mx1); mx2 = grp_max(mx2);
            if ((lane & 3) == 0) {
                rmarr[r1 * 4 + wc] = mx1;
                rmarr[(r1 + 8) * 4 + wc] = mx2;
            }
        }
        CP_WAIT1();
        __syncthreads();                                       // (g) chunk0+srw+rmarr visible

        passB_m(0, chunk0, acc, wid, wr, wc, lane, gm, hq, srw, sKs, rmarr,
                red0, red1, red2, red3);
        CP_WAIT0();
        __syncthreads();                                       // (i) chunk1 visible

        passB_m(1, chunk1, acc, wid, wr, wc, lane, gm, hq, srw, sKs, rmarr,
                red0, red1, red2, red3);
        __syncthreads();                                       // (k)

        if (tid < 64) {
            const float W  = red0[tid * 4] + red0[tid * 4 + 1] + red0[tid * 4 + 2] + red0[tid * 4 + 3];
            const float S2 = red1[tid * 4] + red1[tid * 4 + 1] + red1[tid * 4 + 2] + red1[tid * 4 + 3];
            const float S3 = red2[tid * 4] + red2[tid * 4 + 1] + red2[tid * 4 + 2] + red2[tid * 4 + 3];
            const float T  = red3[tid * 4] + red3[tid * 4 + 1] + red3[tid * 4 + 2] + red3[tid * 4 + 3];
            const float w  = (W + 1e-4f * (S2 + S3) + 2.56e-6f) * (1.f / 256.f);
            const float nm = (T + 1e-4f * ssv) * 0.0625f + 1e-8f;
            scal[tid] = w / nm;
        }
        __syncthreads();                                       // (l)

        const float4* Vg = (const float4*)(V + row0 * KD);
        float4* Og = (float4*)(out + row0 * KD);
#pragma unroll
        for (int t = 0; t < 8; t++) {
            const int i = tid + t * NT;
            const float s = scal[i >> 5];
            float4 v = Vg[i];
            v.x *= s; v.y *= s; v.z *= s; v.w *= s;
            Og[i] = v;
        }
    }
}

// --------------------------------- host -----------------------------------------
extern "C" void kernel_launch(void* const* d_in, const int* in_sizes, int n_in,
                              void* d_out, int out_size) {
    const float* Q   = (const float*)d_in[0];
    const float* K   = (const float*)d_in[1];
    const float* V   = (const float*)d_in[2];
    const float* omg = (const float*)d_in[3];
    float* out = (float*)d_out;

    const int N = in_sizes[0] / KD;
    const int ntiles = N / 64;

    int dev = 0, sms = 148;
    cudaGetDevice(&dev);
    cudaDeviceGetAttribute(&sms, cudaDevAttrMultiProcessorCount, dev);
    const int grid = 2 * sms < ntiles ? 2 * sms : ntiles;

    const size_t smK = (size_t)(BFF_U32 + AFF_U32) * 4 +
                       (size_t)(64 + NF + 256 + 4) * sizeof(float);
    const size_t smF = (size_t)(BFF_U32 + BUF_U32) * 4 +
                       (size_t)(64 + NF + 64 + 256 + 256 * 4 + 64 + 8) * sizeof(float);
    cudaFuncSetAttribute(sp_kpass, cudaFuncAttributeMaxDynamicSharedMemorySize, (int)smK);
    cudaFuncSetAttribute(sp_final, cudaFuncAttributeMaxDynamicSharedMemorySize, (int)smF);

    sp_init<<<1, NF>>>();
    sp_kpass<<<grid, NT, smK>>>(K, omg, ntiles);
    sp_finalize<<<1, NF>>>((float)N * 1e-4f);
    sp_final<<<grid, NT, smF>>>(Q, V, omg, out, ntiles);
}